// round 7
// baseline (speedup 1.0000x reference)
#include <cuda_runtime.h>
#include <cuda_bf16.h>
#include <stdint.h>
#include <math.h>

#define BSZ    2
#define SEQ    2048
#define HID    2048
#define NH     16
#define HD     128
#define MROWS  (BSZ*SEQ)          // 4096
#define NEGBIG (-1000000000.0f)

// ---------------- scratch (device globals; no allocations allowed) ----------
__device__ float g_Q  [MROWS*HID];
__device__ float g_K  [MROWS*HID];
__device__ float g_V  [MROWS*HID];
__device__ float g_CTX[MROWS*HID];
__device__ float g_cos[SEQ*64];
__device__ float g_sin[SEQ*64];

// bf16 hi/lo planes
__device__ __nv_bfloat16 g_hsh[MROWS*HID], g_hsl[MROWS*HID];
__device__ __nv_bfloat16 g_wqh[HID*HID],  g_wql[HID*HID];
__device__ __nv_bfloat16 g_wkh[HID*HID],  g_wkl[HID*HID];
__device__ __nv_bfloat16 g_wvh[HID*HID],  g_wvl[HID*HID];
__device__ __nv_bfloat16 g_woh[HID*HID],  g_wol[HID*HID];
__device__ __nv_bfloat16 g_cxh[MROWS*HID], g_cxl[MROWS*HID];

// ---------------- helpers ---------------------------------------------------
__device__ __forceinline__ uint32_t smem_to_u32(const void* p) {
    uint32_t a;
    asm("{ .reg .u64 t; cvta.to.shared.u64 t, %1; cvt.u32.u64 %0, t; }" : "=r"(a) : "l"(p));
    return a;
}
__device__ __forceinline__ uint32_t pk_hi(float x, float y) {
    __nv_bfloat162 t = __floats2bfloat162_rn(x, y);
    return *(uint32_t*)&t;
}
__device__ __forceinline__ float bf16_res(float x) {
    return x - __bfloat162float(__float2bfloat16(x));
}
__device__ __forceinline__ uint32_t pk_lo(float x, float y) {
    __nv_bfloat162 t = __floats2bfloat162_rn(bf16_res(x), bf16_res(y));
    return *(uint32_t*)&t;
}
__device__ __forceinline__ void mma16816(float* c, const uint32_t* a, const uint32_t* b) {
    asm volatile(
        "mma.sync.aligned.m16n8k16.row.col.f32.bf16.bf16.f32 "
        "{%0,%1,%2,%3}, {%4,%5,%6,%7}, {%8,%9}, {%0,%1,%2,%3};\n"
        : "+f"(c[0]), "+f"(c[1]), "+f"(c[2]), "+f"(c[3])
        : "r"(a[0]), "r"(a[1]), "r"(a[2]), "r"(a[3]), "r"(b[0]), "r"(b[1]));
}
#define LDSM_X4(r0, r1, r2, r3, addr) \
    asm volatile("ldmatrix.sync.aligned.m8n8.x4.shared.b16 {%0,%1,%2,%3}, [%4];" \
        : "=r"(r0), "=r"(r1), "=r"(r2), "=r"(r3) : "r"(addr))
#define CP_ASYNC_16(dst, src) \
    asm volatile("cp.async.cg.shared.global [%0], [%1], 16;" :: "r"(dst), "l"(src))
#define CP_ASYNC_COMMIT() asm volatile("cp.async.commit_group;" ::: "memory")
#define CP_ASYNC_WAIT(n)  asm volatile("cp.async.wait_group %0;" :: "n"(n) : "memory")

// ---------------- fp32 -> bf16 hi/lo split ----------------------------------
__global__ __launch_bounds__(256) void convert_split_kernel(
    const float* __restrict__ in, __nv_bfloat16* __restrict__ oh,
    __nv_bfloat16* __restrict__ ol, int n4)
{
    int i = blockIdx.x * 256 + threadIdx.x;
    if (i >= n4) return;
    float4 v = ((const float4*)in)[i];
    ((uint2*)oh)[i] = make_uint2(pk_hi(v.x, v.y), pk_hi(v.z, v.w));
    ((uint2*)ol)[i] = make_uint2(pk_lo(v.x, v.y), pk_lo(v.z, v.w));
}

// =====================================================================
// GEMM: C[M,2048] = A @ B^T, bf16 hi/lo planes, mma.sync + ldmatrix +
// cp.async double buffer. Tile 128x128x32, 8 warps (warp tile 64x32).
// =====================================================================
#define GP 40                           // smem pitch in halves (80 B)
#define PLANE_B 10240                   // 128 * 80
#define STAGE_B (4*PLANE_B)             // Ah, Al, Bh, Bl
#define GEMM_SMEM (2*STAGE_B)           // 81920

__device__ __forceinline__ void fill_stage_async(uint32_t base, int s,
    const __nv_bfloat16* __restrict__ Ah, const __nv_bfloat16* __restrict__ Al,
    const __nv_bfloat16* __restrict__ Bh, const __nv_bfloat16* __restrict__ Bl,
    int m0, int n0, int tid)
{
    const __nv_bfloat16* gp[4] = {Ah, Al, Bh, Bl};
    const int rb[4] = {m0, m0, n0, n0};
#pragma unroll
    for (int p = 0; p < 4; p++) {
        uint32_t pl = base + p * PLANE_B;
        const __nv_bfloat16* g = gp[p];
#pragma unroll
        for (int j = 0; j < 2; j++) {
            int chunk = tid + j * 256;          // 0..511
            int row = chunk >> 2, cg = chunk & 3;
            uint32_t so = pl + row * 80 + cg * 16;
            const void* gptr = g + (size_t)(rb[p] + row) * HID + s * 32 + cg * 8;
            CP_ASYNC_16(so, gptr);
        }
    }
    CP_ASYNC_COMMIT();
}

__global__ __launch_bounds__(256) void gemm_bf16_tc(
    const __nv_bfloat16* __restrict__ Ah, const __nv_bfloat16* __restrict__ Al,
    const __nv_bfloat16* __restrict__ Bh, const __nv_bfloat16* __restrict__ Bl,
    float* __restrict__ C)
{
    extern __shared__ __align__(16) char smem[];
    const uint32_t sb = smem_to_u32(smem);
    const int tid = threadIdx.x, wid = tid >> 5, lane = tid & 31;
    const int gid = lane >> 2, tig = lane & 3;
    const int m0 = blockIdx.y * 128, n0 = blockIdx.x * 128;
    const int m0w = (wid & 1) * 64, n0w = (wid >> 1) * 32;

    float acc[4][4][4];
#pragma unroll
    for (int i = 0; i < 4; i++)
#pragma unroll
        for (int j = 0; j < 4; j++)
#pragma unroll
            for (int r = 0; r < 4; r++) acc[i][j][r] = 0.0f;

    // lane-derived ldmatrix source rows/cols (in halves)
    const int a_row = m0w + (lane & 15);
    const int a_col = (lane >> 4) << 3;
    const int b_row = n0w + (lane & 7) + ((lane & 16) >> 1);
    const int b_col = lane & 8;

    const int NIT = HID / 32;   // 64
    fill_stage_async(sb, 0, Ah, Al, Bh, Bl, m0, n0, tid);

    for (int it = 0; it < NIT; ++it) {
        if (it + 1 < NIT) {
            fill_stage_async(sb + ((it + 1) & 1) * STAGE_B, it + 1,
                             Ah, Al, Bh, Bl, m0, n0, tid);
            CP_ASYNC_WAIT(1);
        } else {
            CP_ASYNC_WAIT(0);
        }
        __syncthreads();

        const uint32_t st  = sb + (it & 1) * STAGE_B;
        const uint32_t pAh = st, pAl = st + PLANE_B;
        const uint32_t pBh = st + 2 * PLANE_B, pBl = st + 3 * PLANE_B;

#pragma unroll
        for (int ks = 0; ks < 2; ks++) {
            const int kb = ks * 16;
            uint32_t afh[4][4], afl[4][4], bfh[4][2], bfl[4][2];
#pragma unroll
            for (int mi = 0; mi < 4; mi++) {
                uint32_t off = (uint32_t)(((a_row + mi * 16) * GP + kb + a_col) * 2);
                LDSM_X4(afh[mi][0], afh[mi][1], afh[mi][2], afh[mi][3], pAh + off);
                LDSM_X4(afl[mi][0], afl[mi][1], afl[mi][2], afl[mi][3], pAl + off);
            }
#pragma unroll
            for (int nj = 0; nj < 2; nj++) {
                uint32_t off = (uint32_t)(((b_row + nj * 16) * GP + kb + b_col) * 2);
                LDSM_X4(bfh[2*nj][0], bfh[2*nj][1], bfh[2*nj+1][0], bfh[2*nj+1][1], pBh + off);
                LDSM_X4(bfl[2*nj][0], bfl[2*nj][1], bfl[2*nj+1][0], bfl[2*nj+1][1], pBl + off);
            }
#pragma unroll
            for (int mi = 0; mi < 4; mi++)
#pragma unroll
                for (int ni = 0; ni < 4; ni++) {
                    mma16816(acc[mi][ni], afh[mi], bfh[ni]);
                    mma16816(acc[mi][ni], afh[mi], bfl[ni]);
                    mma16816(acc[mi][ni], afl[mi], bfh[ni]);
                }
        }
        __syncthreads();
    }

    // epilogue
#pragma unroll
    for (int mi = 0; mi < 4; mi++) {
#pragma unroll
        for (int ni = 0; ni < 4; ni++) {
            int row = m0 + m0w + mi * 16 + gid;
            int col = n0 + n0w + ni * 8 + tig * 2;
            float* c = acc[mi][ni];
            *(float2*)(C + (size_t)row * HID + col)       = make_float2(c[0], c[1]);
            *(float2*)(C + (size_t)(row + 8) * HID + col) = make_float2(c[2], c[3]);
        }
    }
}

// ---------------- RoPE tables (double precision, fast-math-proof) -----------
__global__ void rope_table_kernel()
{
    int t = blockIdx.x;
    int i = threadIdx.x;
    double invf = exp(-((double)i / 64.0) * log(10000.0));
    double ang  = (double)t * invf;
    double sd, cd;
    sincos(ang, &sd, &cd);
    g_cos[t * 64 + i] = (float)cd;
    g_sin[t * 64 + i] = (float)sd;
}

// ---------------- RoPE apply (in-place on Q/K, layout [b,s,h,d]) ------------
__global__ __launch_bounds__(256) void rope_apply_kernel(const int* __restrict__ pos)
{
    int gid  = blockIdx.x * 256 + threadIdx.x;
    int i    = gid & 63;
    int hrow = gid >> 6;
    int s    = (hrow / NH) % SEQ;
    int p    = pos[s];
    float c  = g_cos[p * 64 + i];
    float sn = g_sin[p * 64 + i];
    float* ptr = (blockIdx.y ? g_K : g_Q) + (size_t)hrow * HD;
    float x1 = ptr[i];
    float x2 = ptr[i + 64];
    ptr[i]      = x1 * c - x2 * sn;
    ptr[i + 64] = x2 * c + x1 * sn;
}

// ---------------- Flash attention (fp32, causal, online softmax) ------------
#define FBM 64
#define FBN 64
#define QPITCH 132
#define PPITCH 68
#define FLASH_SMEM ((FBM*QPITCH*2 + FBN*PPITCH) * sizeof(float))

__global__ __launch_bounds__(256) void flash_kernel(
    const float* __restrict__ Q, const float* __restrict__ K,
    const float* __restrict__ V, float* __restrict__ CTX)
{
    extern __shared__ float sm[];
    float* Qs  = sm;
    float* KVs = sm + FBM * QPITCH;
    float* Pst = KVs + FBM * QPITCH;

    const int tid = threadIdx.x;
    const int b   = blockIdx.y / NH;
    const int h   = blockIdx.y % NH;
    const int qt  = blockIdx.x;
    const int qm0 = qt * FBM;

    const int trow = tid >> 4;
    const int tcol = tid & 15;

    const float scale = 0.08838834764831845f;

#pragma unroll
    for (int i = 0; i < 8; i++) {
        int f4  = tid + i * 256;
        int row = f4 >> 5;
        int col = (f4 & 31) << 2;
        size_t g = ((size_t)(b * SEQ + qm0 + row) * NH + h) * HD + col;
        float4 v = *(const float4*)(Q + g);
        v.x *= scale; v.y *= scale; v.z *= scale; v.w *= scale;
        *(float4*)&Qs[row * QPITCH + col] = v;
    }

    float m_i[4], l_i[4], accv[4][8];
#pragma unroll
    for (int i = 0; i < 4; i++) {
        m_i[i] = -3.0e38f; l_i[i] = 0.0f;
#pragma unroll
        for (int j = 0; j < 8; j++) accv[i][j] = 0.0f;
    }

    __syncthreads();

    for (int kt = 0; kt <= qt; kt++) {
        const int kn0 = kt * FBN;
#pragma unroll
        for (int i = 0; i < 8; i++) {
            int f4  = tid + i * 256;
            int row = f4 >> 5;
            int col = (f4 & 31) << 2;
            size_t g = ((size_t)(b * SEQ + kn0 + row) * NH + h) * HD + col;
            *(float4*)&KVs[row * QPITCH + col] = *(const float4*)(K + g);
        }
        __syncthreads();

        float sv[4][4];
#pragma unroll
        for (int i = 0; i < 4; i++)
#pragma unroll
            for (int j = 0; j < 4; j++) sv[i][j] = 0.0f;

        for (int d4 = 0; d4 < HD; d4 += 4) {
            float4 qv[4], kv[4];
#pragma unroll
            for (int i = 0; i < 4; i++)
                qv[i] = *(const float4*)&Qs[(trow * 4 + i) * QPITCH + d4];
#pragma unroll
            for (int j = 0; j < 4; j++)
                kv[j] = *(const float4*)&KVs[(tcol * 4 + j) * QPITCH + d4];
#pragma unroll
            for (int i = 0; i < 4; i++)
#pragma unroll
                for (int j = 0; j < 4; j++) {
                    sv[i][j] = fmaf(qv[i].x, kv[j].x, sv[i][j]);
                    sv[i][j] = fmaf(qv[i].y, kv[j].y, sv[i][j]);
                    sv[i][j] = fmaf(qv[i].z, kv[j].z, sv[i][j]);
                    sv[i][j] = fmaf(qv[i].w, kv[j].w, sv[i][j]);
                }
        }

        if (kt == qt) {
#pragma unroll
            for (int i = 0; i < 4; i++) {
                int qr = qm0 + trow * 4 + i;
#pragma unroll
                for (int j = 0; j < 4; j++) {
                    int kc = kn0 + tcol * 4 + j;
                    if (kc > qr) sv[i][j] += NEGBIG;
                }
            }
        }

        float p[4][4];
#pragma unroll
        for (int i = 0; i < 4; i++) {
            float rm = fmaxf(fmaxf(sv[i][0], sv[i][1]), fmaxf(sv[i][2], sv[i][3]));
#pragma unroll
            for (int off = 8; off > 0; off >>= 1)
                rm = fmaxf(rm, __shfl_xor_sync(0xffffffffu, rm, off));
            float mnew = fmaxf(m_i[i], rm);
            float corr = __expf(m_i[i] - mnew);
            float rs = 0.0f;
#pragma unroll
            for (int j = 0; j < 4; j++) {
                p[i][j] = __expf(sv[i][j] - mnew);
                rs += p[i][j];
            }
#pragma unroll
            for (int off = 8; off > 0; off >>= 1)
                rs += __shfl_xor_sync(0xffffffffu, rs, off);
            l_i[i] = l_i[i] * corr + rs;
            m_i[i] = mnew;
#pragma unroll
            for (int j = 0; j < 8; j++) accv[i][j] *= corr;
        }

#pragma unroll
        for (int j = 0; j < 4; j++)
#pragma unroll
            for (int i = 0; i < 4; i++)
                Pst[(tcol * 4 + j) * PPITCH + trow * 4 + i] = p[i][j];

        __syncthreads();

#pragma unroll
        for (int i = 0; i < 8; i++) {
            int f4  = tid + i * 256;
            int row = f4 >> 5;
            int col = (f4 & 31) << 2;
            size_t g = ((size_t)(b * SEQ + kn0 + row) * NH + h) * HD + col;
            *(float4*)&KVs[row * QPITCH + col] = *(const float4*)(V + g);
        }
        __syncthreads();

        for (int c = 0; c < FBN; c++) {
            float4 pv = *(const float4*)&Pst[c * PPITCH + trow * 4];
            float4 v0 = *(const float4*)&KVs[c * QPITCH + tcol * 8];
            float4 v1 = *(const float4*)&KVs[c * QPITCH + tcol * 8 + 4];
            float pr[4] = {pv.x, pv.y, pv.z, pv.w};
#pragma unroll
            for (int i = 0; i < 4; i++) {
                accv[i][0] = fmaf(pr[i], v0.x, accv[i][0]);
                accv[i][1] = fmaf(pr[i], v0.y, accv[i][1]);
                accv[i][2] = fmaf(pr[i], v0.z, accv[i][2]);
                accv[i][3] = fmaf(pr[i], v0.w, accv[i][3]);
                accv[i][4] = fmaf(pr[i], v1.x, accv[i][4]);
                accv[i][5] = fmaf(pr[i], v1.y, accv[i][5]);
                accv[i][6] = fmaf(pr[i], v1.z, accv[i][6]);
                accv[i][7] = fmaf(pr[i], v1.w, accv[i][7]);
            }
        }
        __syncthreads();
    }

#pragma unroll
    for (int i = 0; i < 4; i++) {
        float inv = 1.0f / l_i[i];
        int qr = qm0 + trow * 4 + i;
        size_t g = ((size_t)(b * SEQ + qr) * NH + h) * HD + tcol * 8;
        float4 o0 = make_float4(accv[i][0]*inv, accv[i][1]*inv, accv[i][2]*inv, accv[i][3]*inv);
        float4 o1 = make_float4(accv[i][4]*inv, accv[i][5]*inv, accv[i][6]*inv, accv[i][7]*inv);
        *(float4*)(CTX + g)     = o0;
        *(float4*)(CTX + g + 4) = o1;
    }
}

// ---------------- launch --------------------------------------------------
extern "C" void kernel_launch(void* const* d_in, const int* in_sizes, int n_in,
                              void* d_out, int out_size)
{
    const float* hs = (const float*)d_in[0];
    const float* Wq = (const float*)d_in[1];
    const float* Wk = (const float*)d_in[2];
    const float* Wv = (const float*)d_in[3];
    const float* Wo = (const float*)d_in[4];
    const int*   pos = (const int*)d_in[6];
    float* out = (float*)d_out;

    float *Qp, *Kp, *Vp, *Cp;
    cudaGetSymbolAddress((void**)&Qp, g_Q);
    cudaGetSymbolAddress((void**)&Kp, g_K);
    cudaGetSymbolAddress((void**)&Vp, g_V);
    cudaGetSymbolAddress((void**)&Cp, g_CTX);

    __nv_bfloat16 *hsh, *hsl, *wqh, *wql, *wkh, *wkl, *wvh, *wvl, *woh, *wol, *cxh, *cxl;
    cudaGetSymbolAddress((void**)&hsh, g_hsh); cudaGetSymbolAddress((void**)&hsl, g_hsl);
    cudaGetSymbolAddress((void**)&wqh, g_wqh); cudaGetSymbolAddress((void**)&wql, g_wql);
    cudaGetSymbolAddress((void**)&wkh, g_wkh); cudaGetSymbolAddress((void**)&wkl, g_wkl);
    cudaGetSymbolAddress((void**)&wvh, g_wvh); cudaGetSymbolAddress((void**)&wvl, g_wvl);
    cudaGetSymbolAddress((void**)&woh, g_woh); cudaGetSymbolAddress((void**)&wol, g_wol);
    cudaGetSymbolAddress((void**)&cxh, g_cxh); cudaGetSymbolAddress((void**)&cxl, g_cxl);

    cudaFuncSetAttribute(flash_kernel, cudaFuncAttributeMaxDynamicSharedMemorySize, (int)FLASH_SMEM);
    cudaFuncSetAttribute(gemm_bf16_tc, cudaFuncAttributeMaxDynamicSharedMemorySize, GEMM_SMEM);

    const int n4_hs = MROWS * HID / 4;
    const int n4_w  = HID * HID / 4;
    convert_split_kernel<<<(n4_hs + 255) / 256, 256>>>(hs, hsh, hsl, n4_hs);
    convert_split_kernel<<<(n4_w  + 255) / 256, 256>>>(Wq, wqh, wql, n4_w);
    convert_split_kernel<<<(n4_w  + 255) / 256, 256>>>(Wk, wkh, wkl, n4_w);
    convert_split_kernel<<<(n4_w  + 255) / 256, 256>>>(Wv, wvh, wvl, n4_w);
    convert_split_kernel<<<(n4_w  + 255) / 256, 256>>>(Wo, woh, wol, n4_w);

    dim3 ggrid(HID / 128, MROWS / 128);   // (16, 32)
    gemm_bf16_tc<<<ggrid, 256, GEMM_SMEM>>>(hsh, hsl, wqh, wql, Qp);
    gemm_bf16_tc<<<ggrid, 256, GEMM_SMEM>>>(hsh, hsl, wkh, wkl, Kp);
    gemm_bf16_tc<<<ggrid, 256, GEMM_SMEM>>>(hsh, hsl, wvh, wvl, Vp);

    rope_table_kernel<<<SEQ, 64>>>();
    rope_apply_kernel<<<dim3((MROWS * NH * 64) / 256, 2), 256>>>(pos);

    flash_kernel<<<dim3(SEQ / FBM, BSZ * NH), 256, FLASH_SMEM>>>(Qp, Kp, Vp, Cp);

    convert_split_kernel<<<(n4_hs + 255) / 256, 256>>>(Cp, cxh, cxl, n4_hs);
    gemm_bf16_tc<<<ggrid, 256, GEMM_SMEM>>>(cxh, cxl, woh, wol, out);
}

// round 9
// speedup vs baseline: 1.9803x; 1.9803x over previous
#include <cuda_runtime.h>
#include <cuda_bf16.h>
#include <stdint.h>
#include <math.h>

#define BSZ    2
#define SEQ    2048
#define HID    2048
#define NH     16
#define HD     128
#define MROWS  (BSZ*SEQ)          // 4096
#define NEGBIG (-1000000000.0f)

// ---------------- scratch (device globals; no allocations allowed) ----------
__device__ float g_Q  [MROWS*HID];
__device__ float g_K  [MROWS*HID];
__device__ float g_V  [MROWS*HID];
__device__ float g_CTX[MROWS*HID];
__device__ float g_cos[SEQ*64];
__device__ float g_sin[SEQ*64];

// bf16 hi/lo planes (GEMM inputs)
__device__ __nv_bfloat16 g_hsh[MROWS*HID], g_hsl[MROWS*HID];
__device__ __nv_bfloat16 g_wqh[HID*HID],  g_wql[HID*HID];
__device__ __nv_bfloat16 g_wkh[HID*HID],  g_wkl[HID*HID];
__device__ __nv_bfloat16 g_wvh[HID*HID],  g_wvl[HID*HID];
__device__ __nv_bfloat16 g_woh[HID*HID],  g_wol[HID*HID];
__device__ __nv_bfloat16 g_cxh[MROWS*HID], g_cxl[MROWS*HID];

// flash bf16 hi/lo planes, head-major [b,h,s,d]
__device__ __nv_bfloat16 g_qh[MROWS*HID], g_ql[MROWS*HID];
__device__ __nv_bfloat16 g_kh[MROWS*HID], g_kl[MROWS*HID];
__device__ __nv_bfloat16 g_vh[MROWS*HID], g_vl[MROWS*HID];

// ---------------- helpers ---------------------------------------------------
__device__ __forceinline__ uint32_t smem_to_u32(const void* p) {
    uint32_t a;
    asm("{ .reg .u64 t; cvta.to.shared.u64 t, %1; cvt.u32.u64 %0, t; }" : "=r"(a) : "l"(p));
    return a;
}
__device__ __forceinline__ uint32_t pk_hi(float x, float y) {
    __nv_bfloat162 t = __floats2bfloat162_rn(x, y);
    return *(uint32_t*)&t;
}
__device__ __forceinline__ float bf16_res(float x) {
    return x - __bfloat162float(__float2bfloat16(x));
}
__device__ __forceinline__ uint32_t pk_lo(float x, float y) {
    __nv_bfloat162 t = __floats2bfloat162_rn(bf16_res(x), bf16_res(y));
    return *(uint32_t*)&t;
}
__device__ __forceinline__ void mma16816(float* c, const uint32_t* a, const uint32_t* b) {
    asm volatile(
        "mma.sync.aligned.m16n8k16.row.col.f32.bf16.bf16.f32 "
        "{%0,%1,%2,%3}, {%4,%5,%6,%7}, {%8,%9}, {%0,%1,%2,%3};\n"
        : "+f"(c[0]), "+f"(c[1]), "+f"(c[2]), "+f"(c[3])
        : "r"(a[0]), "r"(a[1]), "r"(a[2]), "r"(a[3]), "r"(b[0]), "r"(b[1]));
}
#define LDSM_X4(r0, r1, r2, r3, addr) \
    asm volatile("ldmatrix.sync.aligned.m8n8.x4.shared.b16 {%0,%1,%2,%3}, [%4];" \
        : "=r"(r0), "=r"(r1), "=r"(r2), "=r"(r3) : "r"(addr))
#define LDSM_X4_T(r0, r1, r2, r3, addr) \
    asm volatile("ldmatrix.sync.aligned.m8n8.x4.trans.shared.b16 {%0,%1,%2,%3}, [%4];" \
        : "=r"(r0), "=r"(r1), "=r"(r2), "=r"(r3) : "r"(addr))
#define CP_ASYNC_16(dst, src) \
    asm volatile("cp.async.cg.shared.global [%0], [%1], 16;" :: "r"(dst), "l"(src))
#define CP_ASYNC_COMMIT() asm volatile("cp.async.commit_group;" ::: "memory")
#define CP_ASYNC_WAIT(n)  asm volatile("cp.async.wait_group %0;" :: "n"(n) : "memory")

// ---------------- fp32 -> bf16 hi/lo split ----------------------------------
__global__ __launch_bounds__(256) void convert_split_kernel(
    const float* __restrict__ in, __nv_bfloat16* __restrict__ oh,
    __nv_bfloat16* __restrict__ ol, int n4)
{
    int i = blockIdx.x * 256 + threadIdx.x;
    if (i >= n4) return;
    float4 v = ((const float4*)in)[i];
    ((uint2*)oh)[i] = make_uint2(pk_hi(v.x, v.y), pk_hi(v.z, v.w));
    ((uint2*)ol)[i] = make_uint2(pk_lo(v.x, v.y), pk_lo(v.z, v.w));
}

// =====================================================================
// GEMM (unchanged from R7): C = A @ B^T, bf16 hi/lo, mma.sync+ldmatrix
// =====================================================================
#define GP 40
#define PLANE_B 10240
#define STAGE_B (4*PLANE_B)
#define GEMM_SMEM (2*STAGE_B)

__device__ __forceinline__ void fill_stage_async(uint32_t base, int s,
    const __nv_bfloat16* __restrict__ Ah, const __nv_bfloat16* __restrict__ Al,
    const __nv_bfloat16* __restrict__ Bh, const __nv_bfloat16* __restrict__ Bl,
    int m0, int n0, int tid)
{
    const __nv_bfloat16* gp[4] = {Ah, Al, Bh, Bl};
    const int rb[4] = {m0, m0, n0, n0};
#pragma unroll
    for (int p = 0; p < 4; p++) {
        uint32_t pl = base + p * PLANE_B;
        const __nv_bfloat16* g = gp[p];
#pragma unroll
        for (int j = 0; j < 2; j++) {
            int chunk = tid + j * 256;
            int row = chunk >> 2, cg = chunk & 3;
            uint32_t so = pl + row * 80 + cg * 16;
            const void* gptr = g + (size_t)(rb[p] + row) * HID + s * 32 + cg * 8;
            CP_ASYNC_16(so, gptr);
        }
    }
    CP_ASYNC_COMMIT();
}

__global__ __launch_bounds__(256) void gemm_bf16_tc(
    const __nv_bfloat16* __restrict__ Ah, const __nv_bfloat16* __restrict__ Al,
    const __nv_bfloat16* __restrict__ Bh, const __nv_bfloat16* __restrict__ Bl,
    float* __restrict__ C)
{
    extern __shared__ __align__(16) char smem[];
    const uint32_t sb = smem_to_u32(smem);
    const int tid = threadIdx.x, wid = tid >> 5, lane = tid & 31;
    const int gid = lane >> 2, tig = lane & 3;
    const int m0 = blockIdx.y * 128, n0 = blockIdx.x * 128;
    const int m0w = (wid & 1) * 64, n0w = (wid >> 1) * 32;

    float acc[4][4][4];
#pragma unroll
    for (int i = 0; i < 4; i++)
#pragma unroll
        for (int j = 0; j < 4; j++)
#pragma unroll
            for (int r = 0; r < 4; r++) acc[i][j][r] = 0.0f;

    const int a_row = m0w + (lane & 15);
    const int a_col = (lane >> 4) << 3;
    const int b_row = n0w + (lane & 7) + ((lane & 16) >> 1);
    const int b_col = lane & 8;

    const int NIT = HID / 32;
    fill_stage_async(sb, 0, Ah, Al, Bh, Bl, m0, n0, tid);

    for (int it = 0; it < NIT; ++it) {
        if (it + 1 < NIT) {
            fill_stage_async(sb + ((it + 1) & 1) * STAGE_B, it + 1,
                             Ah, Al, Bh, Bl, m0, n0, tid);
            CP_ASYNC_WAIT(1);
        } else {
            CP_ASYNC_WAIT(0);
        }
        __syncthreads();

        const uint32_t st  = sb + (it & 1) * STAGE_B;
        const uint32_t pAh = st, pAl = st + PLANE_B;
        const uint32_t pBh = st + 2 * PLANE_B, pBl = st + 3 * PLANE_B;

#pragma unroll
        for (int ks = 0; ks < 2; ks++) {
            const int kb = ks * 16;
            uint32_t afh[4][4], afl[4][4], bfh[4][2], bfl[4][2];
#pragma unroll
            for (int mi = 0; mi < 4; mi++) {
                uint32_t off = (uint32_t)(((a_row + mi * 16) * GP + kb + a_col) * 2);
                LDSM_X4(afh[mi][0], afh[mi][1], afh[mi][2], afh[mi][3], pAh + off);
                LDSM_X4(afl[mi][0], afl[mi][1], afl[mi][2], afl[mi][3], pAl + off);
            }
#pragma unroll
            for (int nj = 0; nj < 2; nj++) {
                uint32_t off = (uint32_t)(((b_row + nj * 16) * GP + kb + b_col) * 2);
                LDSM_X4(bfh[2*nj][0], bfh[2*nj][1], bfh[2*nj+1][0], bfh[2*nj+1][1], pBh + off);
                LDSM_X4(bfl[2*nj][0], bfl[2*nj][1], bfl[2*nj+1][0], bfl[2*nj+1][1], pBl + off);
            }
#pragma unroll
            for (int mi = 0; mi < 4; mi++)
#pragma unroll
                for (int ni = 0; ni < 4; ni++) {
                    mma16816(acc[mi][ni], afh[mi], bfh[ni]);
                    mma16816(acc[mi][ni], afh[mi], bfl[ni]);
                    mma16816(acc[mi][ni], afl[mi], bfh[ni]);
                }
        }
        __syncthreads();
    }

#pragma unroll
    for (int mi = 0; mi < 4; mi++) {
#pragma unroll
        for (int ni = 0; ni < 4; ni++) {
            int row = m0 + m0w + mi * 16 + gid;
            int col = n0 + n0w + ni * 8 + tig * 2;
            float* c = acc[mi][ni];
            *(float2*)(C + (size_t)row * HID + col)       = make_float2(c[0], c[1]);
            *(float2*)(C + (size_t)(row + 8) * HID + col) = make_float2(c[2], c[3]);
        }
    }
}

// ---------------- RoPE tables ------------------------------------------------
__global__ void rope_table_kernel()
{
    int t = blockIdx.x;
    int i = threadIdx.x;
    double invf = exp(-((double)i / 64.0) * log(10000.0));
    double ang  = (double)t * invf;
    double sd, cd;
    sincos(ang, &sd, &cd);
    g_cos[t * 64 + i] = (float)cd;
    g_sin[t * 64 + i] = (float)sd;
}

// ---- RoPE apply + hi/lo split + transpose to [b,h,s,d]; Q scaled -----------
__global__ __launch_bounds__(256) void rope_split_kernel(const int* __restrict__ pos)
{
    int gid  = blockIdx.x * 256 + threadIdx.x;   // over MROWS*NH*64
    int i    = gid & 63;
    int hrow = gid >> 6;                         // (b*SEQ+s)*NH + h
    int h    = hrow % NH;
    int s    = (hrow / NH) % SEQ;
    int b    = hrow / (NH * SEQ);
    int p    = pos[s];
    float c  = g_cos[p * 64 + i];
    float sn = g_sin[p * 64 + i];
    const float* src = (blockIdx.y ? g_K : g_Q) + (size_t)hrow * HD;
    float x1 = src[i];
    float x2 = src[i + 64];
    float r1 = x1 * c - x2 * sn;
    float r2 = x2 * c + x1 * sn;
    if (blockIdx.y == 0) {           // Q gets the 1/sqrt(HD) scale
        r1 *= 0.08838834764831845f;
        r2 *= 0.08838834764831845f;
    }
    size_t base = ((size_t)(b * NH + h) * SEQ + s) * HD;
    __nv_bfloat16* dh = (blockIdx.y ? g_kh : g_qh) + base;
    __nv_bfloat16* dl = (blockIdx.y ? g_kl : g_ql) + base;
    __nv_bfloat16 h1 = __float2bfloat16(r1), h2 = __float2bfloat16(r2);
    dh[i]      = h1;  dl[i]      = __float2bfloat16(r1 - __bfloat162float(h1));
    dh[i + 64] = h2;  dl[i + 64] = __float2bfloat16(r2 - __bfloat162float(h2));
}

// ---- V hi/lo split + transpose to [b,h,s,d] --------------------------------
__global__ __launch_bounds__(256) void v_split_kernel()
{
    int t = blockIdx.x * 256 + threadIdx.x;      // over MROWS*NH*32
    int d4   = t & 31;
    int hrow = t >> 5;                            // (b*SEQ+s)*NH + h
    int h    = hrow % NH;
    int s    = (hrow / NH) % SEQ;
    int b    = hrow / (NH * SEQ);
    float4 v = *(const float4*)(g_V + (size_t)hrow * HD + d4 * 4);
    size_t base = ((size_t)(b * NH + h) * SEQ + s) * HD + d4 * 4;
    *(uint2*)(g_vh + base) = make_uint2(pk_hi(v.x, v.y), pk_hi(v.z, v.w));
    *(uint2*)(g_vl + base) = make_uint2(pk_lo(v.x, v.y), pk_lo(v.z, v.w));
}

// =====================================================================
// Flash attention, tensor cores (mma.sync bf16 hi/lo, FA2 style)
// CTA = 64 q rows, 4 warps (warp = m16 x n64), K/V 64-row tiles in smem.
// smem pitch 272 B (ldmatrix conflict-free). P stays in registers.
// =====================================================================
#define FPITCH 272                      // bytes per 128-half row
#define FPLANE 17408                    // 64*272
#define FLASH_SMEM (4*FPLANE)           // Kh,Kl,Vh,Vl = 69632

__global__ __launch_bounds__(128) void flash_tc(
    const __nv_bfloat16* __restrict__ Qh, const __nv_bfloat16* __restrict__ Ql,
    const __nv_bfloat16* __restrict__ Kh, const __nv_bfloat16* __restrict__ Kl,
    const __nv_bfloat16* __restrict__ Vh, const __nv_bfloat16* __restrict__ Vl,
    float* __restrict__ CTX)
{
    extern __shared__ __align__(16) char fsm[];
    const uint32_t sb = smem_to_u32(fsm);
    const int tid = threadIdx.x, wid = tid >> 5, lane = tid & 31;
    const int gid = lane >> 2, tig = lane & 3;
    const int bh = blockIdx.y;                   // b*NH + h
    const int b = bh / NH, h = bh % NH;
    const int qt = blockIdx.x, qm0 = qt * 64;
    const size_t pbase = (size_t)bh * SEQ * HD;

    // ---- prologue: Q tile -> smem -> register a-frags ----
    {
        const __nv_bfloat16* gq[2] = {Qh + pbase + (size_t)qm0 * HD,
                                      Ql + pbase + (size_t)qm0 * HD};
#pragma unroll
        for (int p = 0; p < 2; p++)
#pragma unroll
            for (int j = 0; j < 8; j++) {
                int chunk = tid + j * 128;
                int row = chunk >> 4, c = chunk & 15;
                CP_ASYNC_16(sb + p * FPLANE + row * FPITCH + c * 16,
                            gq[p] + (size_t)row * HD + c * 8);
            }
        CP_ASYNC_COMMIT();
        CP_ASYNC_WAIT(0);
        __syncthreads();
    }
    uint32_t qfh[8][4], qfl[8][4];
    {
        const int arow = wid * 16 + (lane & 15);
        const int acol8 = (lane >> 4) << 3;
#pragma unroll
        for (int kk = 0; kk < 8; kk++) {
            uint32_t addr = sb + arow * FPITCH + (kk * 16 + acol8) * 2;
            LDSM_X4(qfh[kk][0], qfh[kk][1], qfh[kk][2], qfh[kk][3], addr);
            LDSM_X4(qfl[kk][0], qfl[kk][1], qfl[kk][2], qfl[kk][3], addr + FPLANE);
        }
    }
    __syncthreads();   // Q smem region now reusable for K

    float out[16][4];
#pragma unroll
    for (int i = 0; i < 16; i++)
#pragma unroll
        for (int r = 0; r < 4; r++) out[i][r] = 0.0f;
    float m0 = -3.0e38f, m1 = -3.0e38f, l0 = 0.0f, l1 = 0.0f;

    const int krow = (lane & 7) + ((lane & 16) >> 1);   // K b-frag row sel
    const int kcol8 = lane & 8;                          // halves
    const int vrow = lane & 15;                          // V trans row sel
    const int vcol8 = (lane >> 4) << 3;                  // halves

    for (int kt = 0; kt <= qt; kt++) {
        const int kn0 = kt * 64;
        // ---- fill K,V hi/lo tiles ----
        {
            const __nv_bfloat16* gsrc[4] = {
                Kh + pbase + (size_t)kn0 * HD, Kl + pbase + (size_t)kn0 * HD,
                Vh + pbase + (size_t)kn0 * HD, Vl + pbase + (size_t)kn0 * HD};
#pragma unroll
            for (int p = 0; p < 4; p++)
#pragma unroll
                for (int j = 0; j < 8; j++) {
                    int chunk = tid + j * 128;
                    int row = chunk >> 4, c = chunk & 15;
                    CP_ASYNC_16(sb + p * FPLANE + row * FPITCH + c * 16,
                                gsrc[p] + (size_t)row * HD + c * 8);
                }
            CP_ASYNC_COMMIT();
            CP_ASYNC_WAIT(0);
            __syncthreads();
        }

        // ---- S = Q K^T (hi/lo 3-term) ----
        float sv[8][4];
#pragma unroll
        for (int i = 0; i < 8; i++)
#pragma unroll
            for (int r = 0; r < 4; r++) sv[i][r] = 0.0f;

#pragma unroll
        for (int kk = 0; kk < 8; kk++) {
#pragma unroll
            for (int np = 0; np < 4; np++) {
                uint32_t kbh[2][2], kbl[2][2];
                uint32_t addr = sb + (np * 16 + krow) * FPITCH + (kk * 16 + kcol8) * 2;
                LDSM_X4(kbh[0][0], kbh[0][1], kbh[1][0], kbh[1][1], addr);
                LDSM_X4(kbl[0][0], kbl[0][1], kbl[1][0], kbl[1][1], addr + FPLANE);
#pragma unroll
                for (int q = 0; q < 2; q++) {
                    int nt = np * 2 + q;
                    mma16816(sv[nt], qfh[kk], kbh[q]);
                    mma16816(sv[nt], qfh[kk], kbl[q]);
                    mma16816(sv[nt], qfl[kk], kbh[q]);
                }
            }
        }

        // ---- causal mask on diagonal tile ----
        if (kt == qt) {
            int row0 = qm0 + wid * 16 + gid;
            int row1 = row0 + 8;
#pragma unroll
            for (int nt = 0; nt < 8; nt++) {
                int col = kn0 + nt * 8 + tig * 2;
                if (col     > row0) sv[nt][0] += NEGBIG;
                if (col + 1 > row0) sv[nt][1] += NEGBIG;
                if (col     > row1) sv[nt][2] += NEGBIG;
                if (col + 1 > row1) sv[nt][3] += NEGBIG;
            }
        }

        // ---- online softmax ----
        float rmax0 = -3.0e38f, rmax1 = -3.0e38f;
#pragma unroll
        for (int nt = 0; nt < 8; nt++) {
            rmax0 = fmaxf(rmax0, fmaxf(sv[nt][0], sv[nt][1]));
            rmax1 = fmaxf(rmax1, fmaxf(sv[nt][2], sv[nt][3]));
        }
        rmax0 = fmaxf(rmax0, __shfl_xor_sync(0xffffffffu, rmax0, 1));
        rmax0 = fmaxf(rmax0, __shfl_xor_sync(0xffffffffu, rmax0, 2));
        rmax1 = fmaxf(rmax1, __shfl_xor_sync(0xffffffffu, rmax1, 1));
        rmax1 = fmaxf(rmax1, __shfl_xor_sync(0xffffffffu, rmax1, 2));
        float mn0 = fmaxf(m0, rmax0), mn1 = fmaxf(m1, rmax1);
        float cr0 = __expf(m0 - mn0), cr1 = __expf(m1 - mn1);
        float rs0 = 0.0f, rs1 = 0.0f;
#pragma unroll
        for (int nt = 0; nt < 8; nt++) {
            sv[nt][0] = __expf(sv[nt][0] - mn0);
            sv[nt][1] = __expf(sv[nt][1] - mn0);
            sv[nt][2] = __expf(sv[nt][2] - mn1);
            sv[nt][3] = __expf(sv[nt][3] - mn1);
            rs0 += sv[nt][0] + sv[nt][1];
            rs1 += sv[nt][2] + sv[nt][3];
        }
        rs0 += __shfl_xor_sync(0xffffffffu, rs0, 1);
        rs0 += __shfl_xor_sync(0xffffffffu, rs0, 2);
        rs1 += __shfl_xor_sync(0xffffffffu, rs1, 1);
        rs1 += __shfl_xor_sync(0xffffffffu, rs1, 2);
        l0 = l0 * cr0 + rs0;  m0 = mn0;
        l1 = l1 * cr1 + rs1;  m1 = mn1;
#pragma unroll
        for (int nt = 0; nt < 16; nt++) {
            out[nt][0] *= cr0; out[nt][1] *= cr0;
            out[nt][2] *= cr1; out[nt][3] *= cr1;
        }

        // ---- pack P into a-frags (hi/lo) ----
        uint32_t ph[4][4], plo[4][4];
#pragma unroll
        for (int kkv = 0; kkv < 4; kkv++) {
            ph[kkv][0]  = pk_hi(sv[2*kkv][0],   sv[2*kkv][1]);
            ph[kkv][1]  = pk_hi(sv[2*kkv][2],   sv[2*kkv][3]);
            ph[kkv][2]  = pk_hi(sv[2*kkv+1][0], sv[2*kkv+1][1]);
            ph[kkv][3]  = pk_hi(sv[2*kkv+1][2], sv[2*kkv+1][3]);
            plo[kkv][0] = pk_lo(sv[2*kkv][0],   sv[2*kkv][1]);
            plo[kkv][1] = pk_lo(sv[2*kkv][2],   sv[2*kkv][3]);
            plo[kkv][2] = pk_lo(sv[2*kkv+1][0], sv[2*kkv+1][1]);
            plo[kkv][3] = pk_lo(sv[2*kkv+1][2], sv[2*kkv+1][3]);
        }

        // ---- O += P V (hi/lo 3-term), V via ldmatrix.trans ----
#pragma unroll
        for (int kkv = 0; kkv < 4; kkv++) {
#pragma unroll
            for (int np = 0; np < 8; np++) {
                uint32_t vbh[2][2], vbl[2][2];
                uint32_t addr = sb + 2 * FPLANE
                              + (kkv * 16 + vrow) * FPITCH + (np * 16 + vcol8) * 2;
                LDSM_X4_T(vbh[0][0], vbh[0][1], vbh[1][0], vbh[1][1], addr);
                LDSM_X4_T(vbl[0][0], vbl[0][1], vbl[1][0], vbl[1][1], addr + FPLANE);
#pragma unroll
                for (int q = 0; q < 2; q++) {
                    int nt = np * 2 + q;
                    mma16816(out[nt], ph[kkv], vbh[q]);
                    mma16816(out[nt], ph[kkv], vbl[q]);
                    mma16816(out[nt], plo[kkv], vbh[q]);
                }
            }
        }
        __syncthreads();   // protect smem before next fill
    }

    // ---- epilogue: normalize, write CTX [b,s,h,d] ----
    float inv0 = 1.0f / l0, inv1 = 1.0f / l1;
    int row0 = qm0 + wid * 16 + gid;
    int row1 = row0 + 8;
#pragma unroll
    for (int nt = 0; nt < 16; nt++) {
        int col = nt * 8 + tig * 2;
        *(float2*)(CTX + ((size_t)(b * SEQ + row0) * NH + h) * HD + col)
            = make_float2(out[nt][0] * inv0, out[nt][1] * inv0);
        *(float2*)(CTX + ((size_t)(b * SEQ + row1) * NH + h) * HD + col)
            = make_float2(out[nt][2] * inv1, out[nt][3] * inv1);
    }
}

// ---------------- launch --------------------------------------------------
extern "C" void kernel_launch(void* const* d_in, const int* in_sizes, int n_in,
                              void* d_out, int out_size)
{
    const float* hs = (const float*)d_in[0];
    const float* Wq = (const float*)d_in[1];
    const float* Wk = (const float*)d_in[2];
    const float* Wv = (const float*)d_in[3];
    const float* Wo = (const float*)d_in[4];
    const int*   pos = (const int*)d_in[6];
    float* out = (float*)d_out;

    float *Qp, *Kp, *Vp, *Cp;
    cudaGetSymbolAddress((void**)&Qp, g_Q);
    cudaGetSymbolAddress((void**)&Kp, g_K);
    cudaGetSymbolAddress((void**)&Vp, g_V);
    cudaGetSymbolAddress((void**)&Cp, g_CTX);

    __nv_bfloat16 *hsh, *hsl, *wqh, *wql, *wkh, *wkl, *wvh, *wvl, *woh, *wol, *cxh, *cxl;
    cudaGetSymbolAddress((void**)&hsh, g_hsh); cudaGetSymbolAddress((void**)&hsl, g_hsl);
    cudaGetSymbolAddress((void**)&wqh, g_wqh); cudaGetSymbolAddress((void**)&wql, g_wql);
    cudaGetSymbolAddress((void**)&wkh, g_wkh); cudaGetSymbolAddress((void**)&wkl, g_wkl);
    cudaGetSymbolAddress((void**)&wvh, g_wvh); cudaGetSymbolAddress((void**)&wvl, g_wvl);
    cudaGetSymbolAddress((void**)&woh, g_woh); cudaGetSymbolAddress((void**)&wol, g_wol);
    cudaGetSymbolAddress((void**)&cxh, g_cxh); cudaGetSymbolAddress((void**)&cxl, g_cxl);

    __nv_bfloat16 *qh, *ql, *kh, *kl, *vh, *vl;
    cudaGetSymbolAddress((void**)&qh, g_qh); cudaGetSymbolAddress((void**)&ql, g_ql);
    cudaGetSymbolAddress((void**)&kh, g_kh); cudaGetSymbolAddress((void**)&kl, g_kl);
    cudaGetSymbolAddress((void**)&vh, g_vh); cudaGetSymbolAddress((void**)&vl, g_vl);

    cudaFuncSetAttribute(flash_tc, cudaFuncAttributeMaxDynamicSharedMemorySize, (int)FLASH_SMEM);
    cudaFuncSetAttribute(gemm_bf16_tc, cudaFuncAttributeMaxDynamicSharedMemorySize, GEMM_SMEM);

    const int n4_hs = MROWS * HID / 4;
    const int n4_w  = HID * HID / 4;
    convert_split_kernel<<<(n4_hs + 255) / 256, 256>>>(hs, hsh, hsl, n4_hs);
    convert_split_kernel<<<(n4_w  + 255) / 256, 256>>>(Wq, wqh, wql, n4_w);
    convert_split_kernel<<<(n4_w  + 255) / 256, 256>>>(Wk, wkh, wkl, n4_w);
    convert_split_kernel<<<(n4_w  + 255) / 256, 256>>>(Wv, wvh, wvl, n4_w);
    convert_split_kernel<<<(n4_w  + 255) / 256, 256>>>(Wo, woh, wol, n4_w);

    dim3 ggrid(HID / 128, MROWS / 128);   // (16, 32)
    gemm_bf16_tc<<<ggrid, 256, GEMM_SMEM>>>(hsh, hsl, wqh, wql, Qp);
    gemm_bf16_tc<<<ggrid, 256, GEMM_SMEM>>>(hsh, hsl, wkh, wkl, Kp);
    gemm_bf16_tc<<<ggrid, 256, GEMM_SMEM>>>(hsh, hsl, wvh, wvl, Vp);

    rope_table_kernel<<<SEQ, 64>>>();
    rope_split_kernel<<<dim3((MROWS * NH * 64) / 256, 2), 256>>>(pos);
    v_split_kernel<<<(MROWS * NH * 32) / 256, 256>>>();

    flash_tc<<<dim3(SEQ / 64, BSZ * NH), 128, FLASH_SMEM>>>(qh, ql, kh, kl, vh, vl, Cp);

    convert_split_kernel<<<(n4_hs + 255) / 256, 256>>>(Cp, cxh, cxl, n4_hs);
    gemm_bf16_tc<<<ggrid, 256, GEMM_SMEM>>>(cxh, cxl, woh, wol, out);
}